// round 1
// baseline (speedup 1.0000x reference)
#include <cuda_runtime.h>
#include <math.h>

#define S_LEN 2048
#define E_DIM 1024
#define NH    16
#define DH    64

// Scratch (allocation-free rule: __device__ globals)
__device__ __align__(16) float g_q[NH * S_LEN * DH];
__device__ __align__(16) float g_k[NH * S_LEN * DH];
__device__ __align__(16) float g_v[NH * S_LEN * DH];
__device__ __align__(16) float g_ao[S_LEN * E_DIM];

// ---------------------------------------------------------------------------
// Kernel 1: QKV projection.  out[h][s][d] = sum_e x[s][e] * W[h][e][d] + b[h][d]
// BM=128, BN=64(=DH), BK=16; 256 threads; 8x4 micro-tile.
// grid = (S/128=16, H=16, 3)
// ---------------------------------------------------------------------------
__global__ __launch_bounds__(256) void qkv_kernel(
    const float* __restrict__ x,
    const float* __restrict__ Wq, const float* __restrict__ bq,
    const float* __restrict__ Wk, const float* __restrict__ bk,
    const float* __restrict__ Wv, const float* __restrict__ bv)
{
    const int h = blockIdx.y;
    const int z = blockIdx.z;
    const float* W    = (z == 0 ? Wq : z == 1 ? Wk : Wv) + (size_t)h * E_DIM * DH;
    const float* bias = (z == 0 ? bq : z == 1 ? bk : bv) + h * DH;
    float* out        = (z == 0 ? g_q : z == 1 ? g_k : g_v) + (size_t)h * S_LEN * DH;

    const int s0 = blockIdx.x * 128;

    __shared__ float As[16][129];   // As[k][m], padded
    __shared__ float Bs[16][64];    // Bs[k][n]

    const int tid = threadIdx.x;
    const int ty = tid >> 4;        // 0..15 -> 8 rows each
    const int tx = tid & 15;        // 0..15 -> 4 cols each

    float acc[8][4];
    #pragma unroll
    for (int i = 0; i < 8; i++)
        #pragma unroll
        for (int j = 0; j < 4; j++) acc[i][j] = 0.f;

    for (int k0 = 0; k0 < E_DIM; k0 += 16) {
        // A: x[s0+m][k0..k0+15] -> As[k][m] (transposed store)
        #pragma unroll
        for (int r = 0; r < 2; r++) {
            int idx4 = tid + 256 * r;        // 512 float4 total
            int m = idx4 >> 2, kq = idx4 & 3;
            float4 v = *(const float4*)&x[(size_t)(s0 + m) * E_DIM + k0 + kq * 4];
            As[kq * 4 + 0][m] = v.x;
            As[kq * 4 + 1][m] = v.y;
            As[kq * 4 + 2][m] = v.z;
            As[kq * 4 + 3][m] = v.w;
        }
        // B: W[k0+k][0..63] -> Bs[k][n]
        {
            int k = tid >> 4, nq = tid & 15;
            *(float4*)&Bs[k][nq * 4] = *(const float4*)&W[(size_t)(k0 + k) * DH + nq * 4];
        }
        __syncthreads();

        #pragma unroll
        for (int k = 0; k < 16; k++) {
            float a[8], b[4];
            #pragma unroll
            for (int i = 0; i < 8; i++) a[i] = As[k][ty * 8 + i];
            float4 b4 = *(const float4*)&Bs[k][tx * 4];
            b[0] = b4.x; b[1] = b4.y; b[2] = b4.z; b[3] = b4.w;
            #pragma unroll
            for (int i = 0; i < 8; i++)
                #pragma unroll
                for (int j = 0; j < 4; j++) acc[i][j] += a[i] * b[j];
        }
        __syncthreads();
    }

    #pragma unroll
    for (int i = 0; i < 8; i++) {
        float4 o;
        o.x = acc[i][0] + bias[tx * 4 + 0];
        o.y = acc[i][1] + bias[tx * 4 + 1];
        o.z = acc[i][2] + bias[tx * 4 + 2];
        o.w = acc[i][3] + bias[tx * 4 + 3];
        *(float4*)&out[(size_t)(s0 + ty * 8 + i) * DH + tx * 4] = o;
    }
}

// ---------------------------------------------------------------------------
// Kernel 2: causal flash attention per head.
// Br = Bc = 64; 256 threads; 4x4 micro-tiles; online softmax.
// grid = (S/64=32, H=16), dynamic smem = 65792 bytes.
// Output written directly to concat layout g_ao[s][h*DH + d].
// ---------------------------------------------------------------------------
__global__ __launch_bounds__(256) void attn_kernel()
{
    extern __shared__ float sm[];
    float* Qs = sm;              // [64][64] : Qs[d][m]   (Q transposed)
    float* Ks = sm + 4096;       // [64][64] : Ks[d][k]   (K transposed)
    float* Vs = sm + 8192;       // [64][64] : Vs[k][d]   (natural)
    float* Ps = sm + 12288;      // [64][65] : Ps[k][m]   (padded)

    const int h  = blockIdx.y;
    const int i0 = blockIdx.x;   // query tile index
    const float* Q = g_q + (size_t)h * S_LEN * DH;
    const float* K = g_k + (size_t)h * S_LEN * DH;
    const float* V = g_v + (size_t)h * S_LEN * DH;

    const int tid = threadIdx.x;
    const int ty = tid >> 4, tx = tid & 15;

    // Load Q tile transposed: Qs[d][m] = Q[i0*64+m][d]
    #pragma unroll
    for (int r = 0; r < 4; r++) {
        int idx4 = tid + 256 * r;       // 1024 float4
        int m = idx4 >> 4, dq = idx4 & 15;
        float4 v = *(const float4*)&Q[(size_t)(i0 * 64 + m) * DH + dq * 4];
        Qs[(dq * 4 + 0) * 64 + m] = v.x;
        Qs[(dq * 4 + 1) * 64 + m] = v.y;
        Qs[(dq * 4 + 2) * 64 + m] = v.z;
        Qs[(dq * 4 + 3) * 64 + m] = v.w;
    }

    float o[4][4], m_i[4], l_i[4];
    #pragma unroll
    for (int i = 0; i < 4; i++) {
        m_i[i] = -1e30f; l_i[i] = 0.f;
        #pragma unroll
        for (int j = 0; j < 4; j++) o[i][j] = 0.f;
    }

    for (int jt = 0; jt <= i0; jt++) {
        __syncthreads();   // Qs visible (iter 0); Ks/Vs free to overwrite (iter>0)

        // Load K tile transposed + V tile natural
        #pragma unroll
        for (int r = 0; r < 4; r++) {
            int idx4 = tid + 256 * r;
            int kk = idx4 >> 4, dq = idx4 & 15;
            float4 kv = *(const float4*)&K[(size_t)(jt * 64 + kk) * DH + dq * 4];
            Ks[(dq * 4 + 0) * 64 + kk] = kv.x;
            Ks[(dq * 4 + 1) * 64 + kk] = kv.y;
            Ks[(dq * 4 + 2) * 64 + kk] = kv.z;
            Ks[(dq * 4 + 3) * 64 + kk] = kv.w;
            *(float4*)&Vs[kk * 64 + dq * 4] =
                *(const float4*)&V[(size_t)(jt * 64 + kk) * DH + dq * 4];
        }
        __syncthreads();

        // S = Q K^T  (64x64x64)
        float sc[4][4];
        #pragma unroll
        for (int i = 0; i < 4; i++)
            #pragma unroll
            for (int j = 0; j < 4; j++) sc[i][j] = 0.f;

        #pragma unroll 4
        for (int d = 0; d < 64; d++) {
            float a[4];
            #pragma unroll
            for (int i = 0; i < 4; i++) a[i] = Qs[d * 64 + ty * 4 + i];
            float4 b4 = *(const float4*)&Ks[d * 64 + tx * 4];
            float b[4] = {b4.x, b4.y, b4.z, b4.w};
            #pragma unroll
            for (int i = 0; i < 4; i++)
                #pragma unroll
                for (int j = 0; j < 4; j++) sc[i][j] += a[i] * b[j];
        }

        // scale + causal mask (only the diagonal tile needs masking)
        const float scale = 0.125f;   // 1/sqrt(64)
        if (jt == i0) {
            #pragma unroll
            for (int i = 0; i < 4; i++) {
                int row = ty * 4 + i;
                #pragma unroll
                for (int j = 0; j < 4; j++) {
                    int col = tx * 4 + j;
                    sc[i][j] = (col <= row) ? sc[i][j] * scale : -1e30f;
                }
            }
        } else {
            #pragma unroll
            for (int i = 0; i < 4; i++)
                #pragma unroll
                for (int j = 0; j < 4; j++) sc[i][j] *= scale;
        }

        // Online softmax (row reductions across the 16-lane tx group)
        #pragma unroll
        for (int i = 0; i < 4; i++) {
            float mr = fmaxf(fmaxf(sc[i][0], sc[i][1]), fmaxf(sc[i][2], sc[i][3]));
            #pragma unroll
            for (int off = 8; off >= 1; off >>= 1)
                mr = fmaxf(mr, __shfl_xor_sync(0xffffffffu, mr, off));
            float mnew = fmaxf(m_i[i], mr);
            float f = __expf(m_i[i] - mnew);
            float rs = 0.f;
            #pragma unroll
            for (int j = 0; j < 4; j++) {
                sc[i][j] = __expf(sc[i][j] - mnew);
                rs += sc[i][j];
            }
            #pragma unroll
            for (int off = 8; off >= 1; off >>= 1)
                rs += __shfl_xor_sync(0xffffffffu, rs, off);
            l_i[i] = l_i[i] * f + rs;
            m_i[i] = mnew;
            #pragma unroll
            for (int j = 0; j < 4; j++) o[i][j] *= f;
            // stage P transposed: Ps[kcol][row]
            #pragma unroll
            for (int j = 0; j < 4; j++)
                Ps[(tx * 4 + j) * 65 + ty * 4 + i] = sc[i][j];
        }
        __syncthreads();

        // O += P V  (64x64x64)
        #pragma unroll 4
        for (int kk = 0; kk < 64; kk++) {
            float a[4];
            #pragma unroll
            for (int i = 0; i < 4; i++) a[i] = Ps[kk * 65 + ty * 4 + i];
            float4 b4 = *(const float4*)&Vs[kk * 64 + tx * 4];
            float b[4] = {b4.x, b4.y, b4.z, b4.w};
            #pragma unroll
            for (int i = 0; i < 4; i++)
                #pragma unroll
                for (int j = 0; j < 4; j++) o[i][j] += a[i] * b[j];
        }
    }

    // Epilogue: normalize + write concat layout
    #pragma unroll
    for (int i = 0; i < 4; i++) {
        float inv = 1.f / l_i[i];
        int row = i0 * 64 + ty * 4 + i;
        float4 ov;
        ov.x = o[i][0] * inv; ov.y = o[i][1] * inv;
        ov.z = o[i][2] * inv; ov.w = o[i][3] * inv;
        *(float4*)&g_ao[(size_t)row * E_DIM + h * DH + tx * 4] = ov;
    }
}

// ---------------------------------------------------------------------------
// Kernel 3: output projection.  out[s][e] = sum_f ao[s][f] * Wo[f][e] + bo[e]
// BM=128, BN=64, BK=16; grid = (16, 16)
// ---------------------------------------------------------------------------
__global__ __launch_bounds__(256) void proj_kernel(
    const float* __restrict__ Wo, const float* __restrict__ bo,
    float* __restrict__ out)
{
    const int s0 = blockIdx.x * 128;
    const int n0 = blockIdx.y * 64;

    __shared__ float As[16][129];
    __shared__ float Bs[16][64];

    const int tid = threadIdx.x;
    const int ty = tid >> 4, tx = tid & 15;

    float acc[8][4];
    #pragma unroll
    for (int i = 0; i < 8; i++)
        #pragma unroll
        for (int j = 0; j < 4; j++) acc[i][j] = 0.f;

    for (int k0 = 0; k0 < E_DIM; k0 += 16) {
        #pragma unroll
        for (int r = 0; r < 2; r++) {
            int idx4 = tid + 256 * r;
            int m = idx4 >> 2, kq = idx4 & 3;
            float4 v = *(const float4*)&g_ao[(size_t)(s0 + m) * E_DIM + k0 + kq * 4];
            As[kq * 4 + 0][m] = v.x;
            As[kq * 4 + 1][m] = v.y;
            As[kq * 4 + 2][m] = v.z;
            As[kq * 4 + 3][m] = v.w;
        }
        {
            int k = tid >> 4, nq = tid & 15;
            *(float4*)&Bs[k][nq * 4] =
                *(const float4*)&Wo[(size_t)(k0 + k) * E_DIM + n0 + nq * 4];
        }
        __syncthreads();

        #pragma unroll
        for (int k = 0; k < 16; k++) {
            float a[8], b[4];
            #pragma unroll
            for (int i = 0; i < 8; i++) a[i] = As[k][ty * 8 + i];
            float4 b4 = *(const float4*)&Bs[k][tx * 4];
            b[0] = b4.x; b[1] = b4.y; b[2] = b4.z; b[3] = b4.w;
            #pragma unroll
            for (int i = 0; i < 8; i++)
                #pragma unroll
                for (int j = 0; j < 4; j++) acc[i][j] += a[i] * b[j];
        }
        __syncthreads();
    }

    #pragma unroll
    for (int i = 0; i < 8; i++) {
        float4 o;
        o.x = acc[i][0] + bo[n0 + tx * 4 + 0];
        o.y = acc[i][1] + bo[n0 + tx * 4 + 1];
        o.z = acc[i][2] + bo[n0 + tx * 4 + 2];
        o.w = acc[i][3] + bo[n0 + tx * 4 + 3];
        *(float4*)&out[(size_t)(s0 + ty * 8 + i) * E_DIM + n0 + tx * 4] = o;
    }
}

// ---------------------------------------------------------------------------
extern "C" void kernel_launch(void* const* d_in, const int* in_sizes, int n_in,
                              void* d_out, int out_size)
{
    const float* x  = (const float*)d_in[0];
    const float* Wq = (const float*)d_in[1];
    const float* bq = (const float*)d_in[2];
    const float* Wk = (const float*)d_in[3];
    const float* bk = (const float*)d_in[4];
    const float* Wv = (const float*)d_in[5];
    const float* bv = (const float*)d_in[6];
    const float* Wo = (const float*)d_in[7];
    const float* bo = (const float*)d_in[8];
    float* out = (float*)d_out;

    (void)in_sizes; (void)n_in; (void)out_size;

    cudaFuncSetAttribute(attn_kernel,
                         cudaFuncAttributeMaxDynamicSharedMemorySize, 65792);

    qkv_kernel<<<dim3(S_LEN / 128, NH, 3), 256>>>(x, Wq, bq, Wk, bk, Wv, bv);
    attn_kernel<<<dim3(S_LEN / 64, NH), 256, 65792>>>();
    proj_kernel<<<dim3(S_LEN / 128, E_DIM / 64), 256>>>(Wo, bo, out);
}